// round 4
// baseline (speedup 1.0000x reference)
#include <cuda_runtime.h>
#include <cuda_bf16.h>
#include <math.h>

#define POOL 7
#define MAXC 15      // max distinct feature columns an ROI can touch (sizes<223, stride 16)

// Robustly read the stride scalar regardless of dtype.
__device__ __forceinline__ float read_stride(const void* p) {
    int iv = *(const int*)p;
    if (iv >= 1 && iv <= 65536) return (float)iv;
    return *(const float*)p;
}

// grid = (2*POOL, N); blockIdx.x = py*2 + channel-half. 128 threads.
// Phase 1: stream the contiguous column slab for rows y0,y1, y-blend into smem.
// Phase 2: 7 px outputs = one x-lerp each from smem.
__global__ void __launch_bounds__(128)
roi_pool_kernel(const float* __restrict__ feat,
                const float* __restrict__ rois,
                const void* __restrict__ stride_p,
                float* __restrict__ out,
                int W, int C4) {
    __shared__ float4 slab[MAXC * 128];   // 30 KB

    const int bx   = blockIdx.x;
    const int py   = bx >> 1;
    const int half = bx & 1;
    const int n    = blockIdx.y;
    const int tid  = threadIdx.x;

    // ---- uniform per-block coordinate math ----
    const float s = read_stride(stride_p);
    const int ymin = (int)(rois[4 * n + 0] / s);
    const int xmin = (int)(rois[4 * n + 1] / s);
    const int ymax = (int)(rois[4 * n + 2] / s);
    const int xmax = (int)(rois[4 * n + 3] / s);

    const int   spany = ymax - ymin;
    const float sy    = (float)(spany + 1) / (float)POOL;
    const float srcy  = (float)py * sy;
    const int   iy0   = (int)floorf(srcy);
    const float dy    = srcy - (float)iy0;
    const int   y0    = ymin + iy0;
    const int   y1    = ymin + min(iy0 + 1, spany);

    const int   spanx = xmax - xmin;
    const float sx    = (float)(spanx + 1) / (float)POOL;
    int   r0[POOL], r1[POOL];
    float dxv[POOL];
#pragma unroll
    for (int px = 0; px < POOL; ++px) {
        const float srcx = (float)px * sx;
        const int   ix0  = (int)floorf(srcx);
        dxv[px] = srcx - (float)ix0;
        r0[px]  = ix0;
        r1[px]  = min(ix0 + 1, spanx);
    }
    int ncols = r1[POOL - 1] + 1;           // columns [xmin .. xmin+ncols-1]
    if (ncols > MAXC) ncols = MAXC;         // safety (should never trigger)

    const int cbase = half * 128;           // which 128-float4 channel half

    // ---- phase 1: bulk load + y-blend into smem (independent loads, high MLP) ----
    const float4* __restrict__ f  = (const float4*)feat;
    const float4* __restrict__ p0 = f + (y0 * W + xmin) * C4 + cbase + tid;
    const float4* __restrict__ p1 = f + (y1 * W + xmin) * C4 + cbase + tid;

#pragma unroll 5
    for (int col = 0; col < ncols; ++col) {
        const float4 t0 = p0[col * C4];
        const float4 t1 = p1[col * C4];
        float4 v;
        v.x = t0.x + (t1.x - t0.x) * dy;
        v.y = t0.y + (t1.y - t0.y) * dy;
        v.z = t0.z + (t1.z - t0.z) * dy;
        v.w = t0.w + (t1.w - t0.w) * dy;
        slab[col * 128 + tid] = v;
    }
    __syncthreads();

    // ---- phase 2: x-lerp from smem, store ----
    float4* __restrict__ o =
        (float4*)out + (n * (POOL * POOL) + py * POOL) * C4 + cbase + tid;

#pragma unroll
    for (int px = 0; px < POOL; ++px) {
        const float4 u  = slab[r0[px] * 128 + tid];
        const float4 v  = slab[r1[px] * 128 + tid];
        const float dx = dxv[px];
        float4 r;
        r.x = u.x + (v.x - u.x) * dx;
        r.y = u.y + (v.y - u.y) * dx;
        r.z = u.z + (v.z - u.z) * dx;
        r.w = u.w + (v.w - u.w) * dx;
        o[px * C4] = r;
    }
}

extern "C" void kernel_launch(void* const* d_in, const int* in_sizes, int n_in,
                              void* d_out, int out_size) {
    const float* feat  = (const float*)d_in[0];   // (1, H, W, C) fp32
    const float* rois  = (const float*)d_in[1];   // (N, 4) fp32
    const void*  strid = d_in[2];                 // scalar

    int N = in_sizes[1] / 4;
    int C = out_size / (N * POOL * POOL);         // 1024
    int HW = in_sizes[0] / C;                     // 4096
    int W = 1;
    while (W * W < HW) W <<= 1;                   // 64 for HW=4096
    if (W * W != HW) {
        W = (int)(sqrtf((float)HW) + 0.5f);       // non-pow2 fallback
    }

    dim3 grid(2 * POOL, N);
    roi_pool_kernel<<<grid, 128>>>(feat, rois, strid, (float*)d_out, W, C / 4);
}

// round 5
// speedup vs baseline: 1.2044x; 1.2044x over previous
#include <cuda_runtime.h>
#include <cuda_bf16.h>
#include <math.h>

#define POOL 7

// Robustly read the stride scalar regardless of dtype.
__device__ __forceinline__ float read_stride(const void* p) {
    int iv = *(const int*)p;
    if (iv >= 1 && iv <= 65536) return (float)iv;
    return *(const float*)p;
}

__device__ __forceinline__ float4 lerp4(float4 a, float4 b, float t) {
    float4 r;
    r.x = a.x + (b.x - a.x) * t;
    r.y = a.y + (b.y - a.y) * t;
    r.z = a.z + (b.z - a.z) * t;
    r.w = a.w + (b.w - a.w) * t;
    return r;
}

// One block per (roi, py). 128 threads; each thread owns TWO float4 channel
// chunks (c = tid and c = tid + C4/2), giving two independent dependency
// chains per thread (2x MLP) while keeping the deduplicated sliding-cache
// traffic (~2*K column loads instead of 28).
__global__ void __launch_bounds__(128)
roi_pool_kernel(const float* __restrict__ feat,
                const float* __restrict__ rois,
                const void* __restrict__ stride_p,
                float* __restrict__ out,
                int W, int C4) {
    const int py = blockIdx.x;     // 0..6
    const int n  = blockIdx.y;     // roi index
    const int tid = threadIdx.x;

    // ---- uniform per-block coordinate math ----
    const float s = read_stride(stride_p);
    const int ymin = (int)(rois[4 * n + 0] / s);
    const int xmin = (int)(rois[4 * n + 1] / s);
    const int ymax = (int)(rois[4 * n + 2] / s);
    const int xmax = (int)(rois[4 * n + 3] / s);

    const int   spany = ymax - ymin;
    const float sy    = (float)(spany + 1) / (float)POOL;
    const float srcy  = (float)py * sy;
    const int   iy0   = (int)floorf(srcy);
    const float dy    = srcy - (float)iy0;
    const int   y0    = ymin + iy0;
    const int   y1    = ymin + min(iy0 + 1, spany);

    const int   spanx = xmax - xmin;
    const float sx    = (float)(spanx + 1) / (float)POOL;
    int   nx0[POOL], nx1[POOL];
    float dxv[POOL];
#pragma unroll
    for (int px = 0; px < POOL; ++px) {
        const float srcx = (float)px * sx;
        const int   ix0  = (int)floorf(srcx);
        dxv[px] = srcx - (float)ix0;
        nx0[px] = xmin + ix0;
        nx1[px] = xmin + min(ix0 + 1, spanx);
    }

    const int h = C4 >> 1;                         // 128 for C4=256
    const float4* __restrict__ f    = (const float4*)feat;
    const float4* __restrict__ row0 = f + y0 * W * C4;   // 32-bit index math
    const float4* __restrict__ row1 = f + y1 * W * C4;
    float4* __restrict__ o = (float4*)out + (n * (POOL * POOL) + py * POOL) * C4;

    const int c0 = tid;            // chunk 0
    const int c1 = tid + h;        // chunk 1 (independent chain)

    // sliding cache of y-blended columns, two chunks per column
    int cA = -1, cB = -1;
    float4 vA0, vB0, vA1, vB1;

#pragma unroll
    for (int px = 0; px < POOL; ++px) {
        const int   x0 = nx0[px];
        const int   x1 = nx1[px];
        const float dx = dxv[px];

        if (x0 != cA) {                    // warp-uniform branches
            if (x0 == cB) { vA0 = vB0; vA1 = vB1; }
            else {
                const int base = x0 * C4;
                const float4 t00 = row0[base + c0];
                const float4 t10 = row1[base + c0];
                const float4 t01 = row0[base + c1];
                const float4 t11 = row1[base + c1];
                vA0 = lerp4(t00, t10, dy);
                vA1 = lerp4(t01, t11, dy);
            }
            cA = x0;
        }
        if (x1 != cB) {
            if (x1 == cA) { vB0 = vA0; vB1 = vA1; }
            else {
                const int base = x1 * C4;
                const float4 t00 = row0[base + c0];
                const float4 t10 = row1[base + c0];
                const float4 t01 = row0[base + c1];
                const float4 t11 = row1[base + c1];
                vB0 = lerp4(t00, t10, dy);
                vB1 = lerp4(t01, t11, dy);
            }
            cB = x1;
        }

        const int ob = px * C4;
        o[ob + c0] = lerp4(vA0, vB0, dx);
        o[ob + c1] = lerp4(vA1, vB1, dx);
    }
}

extern "C" void kernel_launch(void* const* d_in, const int* in_sizes, int n_in,
                              void* d_out, int out_size) {
    const float* feat  = (const float*)d_in[0];   // (1, H, W, C) fp32
    const float* rois  = (const float*)d_in[1];   // (N, 4) fp32
    const void*  strid = d_in[2];                 // scalar

    int N = in_sizes[1] / 4;
    int C = out_size / (N * POOL * POOL);         // 1024
    int HW = in_sizes[0] / C;                     // 4096
    int W = 1;
    while (W * W < HW) W <<= 1;                   // 64 for HW=4096
    if (W * W != HW) {
        W = (int)(sqrtf((float)HW) + 0.5f);       // non-pow2 fallback
    }

    dim3 grid(POOL, N);
    roi_pool_kernel<<<grid, 128>>>(feat, rois, strid, (float*)d_out, W, C / 4);
}